// round 16
// baseline (speedup 1.0000x reference)
#include <cuda_runtime.h>
#include <cuda_bf16.h>
#include <math.h>
#include <stdint.h>

// ---------------- problem shapes ----------------
#define N_ROWS   2048
#define DIM      512
#define NQ       3
#define KQ       8192
#define QK       (NQ * KQ)        // 24576
#define NCLS     16
#define NHB      32               // histogram partial blocks

// ---------------- GEMM tiling -------------------
#define BM   128                  // x rows per CTA
#define BN   128                  // q rows per CTA
#define BK   64                   // bf16 K per stage (128B rows = SW128 atom)
#define NJT  (QK / BN)            // 192 j-tiles
#define NT   (DIM / BK)           // 8 mainloop iters
#define NSTG 3

#define A_ST (BM * BK * 2)        // 16384 bytes/stage
#define B_ST (BN * BK * 2)        // 16384 bytes/stage
#define QTP_OFF  (NSTG * (A_ST + B_ST))         // 98304
#define RED_OFF  (QTP_OFF + 512)
#define RED_PITCH 5
#define SMEM_BYTES (RED_OFF + 2 * BM * RED_PITCH * 4)   // ~104KB

// k_rows config: one warp per row
#define RW_BLOCKS (N_ROWS / 8)    // 256 blocks x 8 warps

// ---------------- static device scratch ----------------
__device__ __align__(16) __nv_bfloat16 g_xb[N_ROWS * DIM];
__device__ __align__(16) __nv_bfloat16 g_qb[QK * DIM];
__device__ float g_pt[NJT * N_ROWS];
__device__ float g_pm[NJT * N_ROWS];
__device__ float g_row[N_ROWS];
__device__ int   g_hpart[NHB * NCLS];
__device__ int   g_meta[4];   // [0]=targets is64, [1]=q_targets is64, [2]=order
__device__ int   g_tick;

__device__ __forceinline__ int load_tgt(const void* p, int i, int is64) {
    if (is64) return (int)((const long long*)p)[i];
    return ((const int*)p)[i];
}

// ---------------- helpers ----------------
__device__ __forceinline__ uint32_t smem_u32(const void* p) {
    uint32_t a;
    asm("{ .reg .u64 t; cvta.to.shared.u64 t, %1; cvt.u32.u64 %0, t; }" : "=r"(a) : "l"(p));
    return a;
}
__device__ __forceinline__ uint32_t swz(uint32_t o) { return o ^ ((o >> 3) & 0x70u); }

__device__ __forceinline__ void cpasync16(uint32_t s, const void* g) {
    asm volatile("cp.async.cg.shared.global [%0], [%1], 16;" :: "r"(s), "l"(g) : "memory");
}
__device__ __forceinline__ void cp_commit() {
    asm volatile("cp.async.commit_group;" ::: "memory");
}
__device__ __forceinline__ void cp_wait0() {
    asm volatile("cp.async.wait_group 0;" ::: "memory");
}
__device__ __forceinline__ void ldm4(uint32_t a, uint32_t& r0, uint32_t& r1,
                                     uint32_t& r2, uint32_t& r3) {
    asm volatile("ldmatrix.sync.aligned.m8n8.x4.shared.b16 {%0,%1,%2,%3}, [%4];"
                 : "=r"(r0), "=r"(r1), "=r"(r2), "=r"(r3) : "r"(a));
}
__device__ __forceinline__ void mma16816(float* c, const uint32_t* a, const uint32_t* b) {
    asm volatile(
        "mma.sync.aligned.m16n8k16.row.col.f32.bf16.bf16.f32 "
        "{%0,%1,%2,%3}, {%4,%5,%6,%7}, {%8,%9}, {%0,%1,%2,%3};"
        : "+f"(c[0]), "+f"(c[1]), "+f"(c[2]), "+f"(c[3])
        : "r"(a[0]), "r"(a[1]), "r"(a[2]), "r"(a[3]), "r"(b[0]), "r"(b[1]));
}

// ---------------- k_pre: meta detection + histogram partials ----------------
__global__ void k_pre(const void* targets, const void* q_targets, const void* order_p) {
    const int b = blockIdx.x, tid = threadIdx.x;
    if (b == NHB) {
        if (tid < 32) {
            unsigned v = ((const unsigned*)targets)[2 * tid + 1];
            unsigned any = __ballot_sync(0xffffffffu, v != 0u);
            if (tid == 0) g_meta[0] = (any == 0u) ? 1 : 0;
        }
        return;
    }
    __shared__ int hist_s[NCLS];
    unsigned w = ((const unsigned*)q_targets)[2 * (tid & 31) + 1];
    unsigned anyq = __ballot_sync(0xffffffffu, w != 0u);
    const int is64q = (anyq == 0u) ? 1 : 0;
    const int order = ((const int*)order_p)[0];   // low dword valid for i32/i64
    if (tid < NCLS) hist_s[tid] = 0;
    __syncthreads();
    const int i = b * 256 + tid;                  // 32*256 = 8192 = KQ
    int v = load_tgt(q_targets, order * KQ + i, is64q);
    atomicAdd(&hist_s[v], 1);
    __syncthreads();
    if (tid < NCLS) g_hpart[b * NCLS + tid] = hist_s[tid];
    if (b == 0 && tid == 0) { g_meta[1] = is64q; g_meta[2] = order; }
}

// ---------------- k_convert: L2-norm + bf16 cast (float4 loads) ----------------
__global__ void k_convert(const float* __restrict__ x, const float* __restrict__ q) {
    int warp = (blockIdx.x * blockDim.x + threadIdx.x) >> 5;
    int lane = threadIdx.x & 31;
    if (warp >= N_ROWS + QK) return;
    const float* src;
    __nv_bfloat16* dst;
    if (warp < N_ROWS) { src = x + (size_t)warp * DIM; dst = g_xb + (size_t)warp * DIM; }
    else { src = q + (size_t)(warp - N_ROWS) * DIM; dst = g_qb + (size_t)(warp - N_ROWS) * DIM; }
    const float4* s4 = (const float4*)src;
    float4 v[4];
    float s = 0.f;
    #pragma unroll
    for (int c = 0; c < 4; c++) {
        v[c] = s4[lane + c * 32];
        s += v[c].x * v[c].x + v[c].y * v[c].y + v[c].z * v[c].z + v[c].w * v[c].w;
    }
    #pragma unroll
    for (int o = 16; o > 0; o >>= 1) s += __shfl_xor_sync(0xffffffffu, s, o);
    float inv = 1.f / fmaxf(sqrtf(s), 1e-12f);
    uint2* d2 = (uint2*)dst;
    #pragma unroll
    for (int c = 0; c < 4; c++) {
        __nv_bfloat162 lo, hi;
        lo.x = __float2bfloat16_rn(v[c].x * inv);
        lo.y = __float2bfloat16_rn(v[c].y * inv);
        hi.x = __float2bfloat16_rn(v[c].z * inv);
        hi.y = __float2bfloat16_rn(v[c].w * inv);
        uint2 o2;
        o2.x = *(uint32_t*)&lo;
        o2.y = *(uint32_t*)&hi;
        d2[lane + c * 32] = o2;
    }
}

// ---------------- k_main: HMMA bf16 GEMM + fused exp epilogue ----------------
__global__ void __launch_bounds__(256, 2)
k_main(const void* __restrict__ targets, const void* __restrict__ q_targets) {
    extern __shared__ char smem_raw[];
    const uint32_t smem = smem_u32(smem_raw);
    const uint32_t aBase = smem;
    const uint32_t bBase = smem + NSTG * A_ST;
    int*   qtp  = (int*)(smem_raw + QTP_OFF);
    float* sm_s = (float*)(smem_raw + RED_OFF);
    float* sm_m = sm_s + BM * RED_PITCH;

    const int tid  = threadIdx.x;
    const int wid  = tid >> 5;
    const int lane = tid & 31;
    const int wm   = wid & 1;          // 2 warp-rows (64 M each)
    const int wn   = wid >> 1;         // 4 warp-cols (32 N each)
    const int i0   = blockIdx.y * BM;
    const int j0   = blockIdx.x * BN;

    const int is64t = g_meta[0];
    const int is64q = g_meta[1];
    const bool otile = (j0 / KQ) == g_meta[2];

    if (otile && tid < BN) qtp[tid] = load_tgt(q_targets, j0 + tid, is64q);

    // per-thread cp.async dest/src bases (immediate offsets per stage after unroll)
    uint32_t dstA[4];
    const char* srcA[4];
    const char* srcB[4];
    #pragma unroll
    for (int l = 0; l < 4; l++) {
        int idx = tid + l * 256, row = idx >> 3, c = idx & 7;
        dstA[l] = swz((uint32_t)(row * 128 + c * 16));
        srcA[l] = (const char*)(g_xb + ((size_t)(i0 + row) * DIM + c * 8));
        srcB[l] = (const char*)(g_qb + ((size_t)(j0 + row) * DIM + c * 8));
    }

    // ldmatrix per-lane byte offsets within a stage (ks -> XOR ks*32)
    uint32_t offA0[4], offB0[2];
    {
        int kc = lane >> 4;                 // 16B half
        #pragma unroll
        for (int m = 0; m < 4; m++) {
            int rowA = wm * 64 + m * 16 + (lane & 15);
            offA0[m] = swz((uint32_t)(rowA * 128 + kc * 16));
        }
        int kc2 = (lane >> 3) & 1;
        #pragma unroll
        for (int p = 0; p < 2; p++) {
            int rowB = wn * 32 + p * 16 + (lane & 7) + ((lane >> 4) & 1) * 8;
            offB0[p] = swz((uint32_t)(rowB * 128 + kc2 * 16));
        }
    }

    // hoisted epilogue row-target loads (hide latency behind the GEMM)
    const int l4  = lane >> 2;
    const int lm4 = lane & 3;
    int tgr[8];
    #pragma unroll
    for (int m = 0; m < 4; m++)
        #pragma unroll
        for (int half = 0; half < 2; half++)
            tgr[m * 2 + half] = load_tgt(targets, i0 + wm * 64 + m * 16 + half * 8 + l4, is64t);

    float c[4][4][4];
    #pragma unroll
    for (int m = 0; m < 4; m++)
        #pragma unroll
        for (int n = 0; n < 4; n++)
            #pragma unroll
            for (int e = 0; e < 4; e++) c[m][n][e] = 0.f;

    // register-double-buffered fragments
    uint32_t afr[2][4][4], bfr[2][4][2];

    // ---- prologue: stages 0,1; wait both, sync, preload ks0 of stage 0 ----
    #pragma unroll
    for (int s = 0; s < 2; s++) {
        #pragma unroll
        for (int l = 0; l < 4; l++) cpasync16(aBase + s * A_ST + dstA[l], srcA[l] + s * 128);
        #pragma unroll
        for (int l = 0; l < 4; l++) cpasync16(bBase + s * B_ST + dstA[l], srcB[l] + s * 128);
        cp_commit();
    }
    cp_wait0();
    __syncthreads();
    #pragma unroll
    for (int m = 0; m < 4; m++)
        ldm4(aBase + offA0[m], afr[0][m][0], afr[0][m][1], afr[0][m][2], afr[0][m][3]);
    #pragma unroll
    for (int p = 0; p < 2; p++)
        ldm4(bBase + offB0[p], bfr[0][2*p][0], bfr[0][2*p][1], bfr[0][2*p+1][0], bfr[0][2*p+1][1]);

    #pragma unroll
    for (int kt = 0; kt < NT; kt++) {
        const uint32_t aS = aBase + (kt % NSTG) * A_ST;
        const uint32_t bS = bBase + (kt % NSTG) * B_ST;
        const uint32_t aN = aBase + ((kt + 1) % NSTG) * A_ST;   // next stage (data already resident)
        const uint32_t bN = bBase + ((kt + 1) % NSTG) * B_ST;

        #pragma unroll
        for (int ks = 0; ks < 4; ks++) {
            const int cur = ks & 1;
            const int nxt = cur ^ 1;
            if (ks < 3) {
                const uint32_t kx = (ks + 1) * 32;
                #pragma unroll
                for (int m = 0; m < 4; m++)
                    ldm4(aS + (offA0[m] ^ kx), afr[nxt][m][0], afr[nxt][m][1],
                         afr[nxt][m][2], afr[nxt][m][3]);
                #pragma unroll
                for (int p = 0; p < 2; p++)
                    ldm4(bS + (offB0[p] ^ kx), bfr[nxt][2*p][0], bfr[nxt][2*p][1],
                         bfr[nxt][2*p+1][0], bfr[nxt][2*p+1][1]);
            } else if (kt + 1 < NT) {
                // cross-iteration prefetch: ks=0 fragments of stage kt+1 (published
                // by bottom-of-(kt-1) wait_group 0 + barrier)
                #pragma unroll
                for (int m = 0; m < 4; m++)
                    ldm4(aN + offA0[m], afr[nxt][m][0], afr[nxt][m][1],
                         afr[nxt][m][2], afr[nxt][m][3]);
                #pragma unroll
                for (int p = 0; p < 2; p++)
                    ldm4(bN + offB0[p], bfr[nxt][2*p][0], bfr[nxt][2*p][1],
                         bfr[nxt][2*p+1][0], bfr[nxt][2*p+1][1]);
            }
            #pragma unroll
            for (int m = 0; m < 4; m++)
                #pragma unroll
                for (int n = 0; n < 4; n++)
                    mma16816(c[m][n], afr[cur][m], bfr[cur][n]);

            // issue next-stage global prefetch after ks0's MMAs (LDSM-priority)
            if (ks == 0 && kt + 2 < NT) {
                const int s = (kt + 2) % NSTG;
                #pragma unroll
                for (int l = 0; l < 4; l++) cpasync16(aBase + s * A_ST + dstA[l], srcA[l] + (kt + 2) * 128);
                #pragma unroll
                for (int l = 0; l < 4; l++) cpasync16(bBase + s * B_ST + dstA[l], srcB[l] + (kt + 2) * 128);
                cp_commit();
            }
        }

        if (kt + 1 < NT) {
            cp_wait0();          // stage kt+2 resident (issued ~1 iter ago)
            __syncthreads();     // publish + protect stage reuse
        }
    }

    // ---- epilogue: exp + per-row (total, masked) partial sums ----
    int qtv[8];
    if (otile) {
        #pragma unroll
        for (int n = 0; n < 4; n++)
            #pragma unroll
            for (int e = 0; e < 2; e++)
                qtv[n * 2 + e] = qtp[wn * 32 + n * 8 + lm4 * 2 + e];
    }
    #pragma unroll
    for (int m = 0; m < 4; m++) {
        #pragma unroll
        for (int half = 0; half < 2; half++) {
            const int rl = wm * 64 + m * 16 + half * 8 + l4;   // local row
            const int tg = tgr[m * 2 + half];
            float s = 0.f, mk = 0.f;
            #pragma unroll
            for (int n = 0; n < 4; n++) {
                #pragma unroll
                for (int e = 0; e < 2; e++) {
                    float ex = __expf(fmaf(4.f, c[m][n][half * 2 + e], -4.f));
                    s += ex;
                    if (otile && qtv[n * 2 + e] == tg) mk += ex;
                }
            }
            s  += __shfl_xor_sync(0xffffffffu, s, 1);
            s  += __shfl_xor_sync(0xffffffffu, s, 2);
            mk += __shfl_xor_sync(0xffffffffu, mk, 1);
            mk += __shfl_xor_sync(0xffffffffu, mk, 2);
            if (lm4 == 0) {
                sm_s[rl * RED_PITCH + wn] = s;
                sm_m[rl * RED_PITCH + wn] = mk;
            }
        }
    }
    __syncthreads();
    if (tid < BM) {
        float tot = 0.f, msk = 0.f;
        #pragma unroll
        for (int w = 0; w < 4; w++) {
            tot += sm_s[tid * RED_PITCH + w];
            msk += sm_m[tid * RED_PITCH + w];
        }
        g_pt[blockIdx.x * N_ROWS + i0 + tid] = tot;
        g_pm[blockIdx.x * N_ROWS + i0 + tid] = msk;
    }
}

// ---------------- k_rows: warp-per-row log terms + ticketed final sum ------
__global__ void __launch_bounds__(256)
k_rows(const void* __restrict__ targets, float* __restrict__ out) {
    const int tid  = threadIdx.x;
    const int wid  = tid >> 5;
    const int lane = tid & 31;
    __shared__ float cntS[NCLS];
    __shared__ int amLast;

    // per-class counts once per block (16 threads x 32 partials, L2-hot)
    if (tid < NCLS) {
        int c = QK;
        #pragma unroll
        for (int b = 0; b < NHB; b++) c -= g_hpart[b * NCLS + tid];
        cntS[tid] = (float)c;
    }
    __syncthreads();

    const int i = blockIdx.x * 8 + wid;    // one warp per row; 256 blocks x 8
    float t = 0.f, m = 0.f;
    #pragma unroll
    for (int u = 0; u < NJT / 32; u++) {   // 6 iters: tiles lane, lane+32, ...
        const int tt = lane + u * 32;
        t += g_pt[tt * N_ROWS + i];
        m += g_pm[tt * N_ROWS + i];
    }
    #pragma unroll
    for (int o = 16; o > 0; o >>= 1) {
        t += __shfl_xor_sync(0xffffffffu, t, o);
        m += __shfl_xor_sync(0xffffffffu, m, o);
    }
    if (lane == 0) {
        int tg = load_tgt(targets, i, g_meta[0]);
        g_row[i] = logf((t - m) / cntS[tg]);
    }

    // ticket: last block performs the deterministic final sum
    __threadfence();
    __syncthreads();
    if (tid == 0) amLast = (atomicAdd(&g_tick, 1) == RW_BLOCKS - 1);
    __syncthreads();
    if (amLast) {
        __shared__ float red[256];
        float s = 0.f;
        for (int k = tid; k < N_ROWS; k += 256) s += g_row[k];
        red[tid] = s;
        __syncthreads();
        for (int st = 128; st > 0; st >>= 1) {
            if (tid < st) red[tid] += red[tid + st];
            __syncthreads();
        }
        if (tid == 0) { out[0] = red[0] / (float)N_ROWS; g_tick = 0; }
    }
}

// ---------------- launch ----------------
extern "C" void kernel_launch(void* const* d_in, const int* in_sizes, int n_in,
                              void* d_out, int out_size) {
    const float* x       = (const float*)d_in[0];
    const float* q       = (const float*)d_in[1];
    const void*  targets = d_in[2];
    const void*  q_tgts  = d_in[3];
    const void*  order_p = d_in[4];

    cudaFuncSetAttribute(k_main, cudaFuncAttributeMaxDynamicSharedMemorySize, SMEM_BYTES);

    k_pre<<<NHB + 1, 256>>>(targets, q_tgts, order_p);
    {
        int total_warps = N_ROWS + QK;              // 26624
        int blocks = (total_warps + 7) / 8;
        k_convert<<<blocks, 256>>>(x, q);
    }
    dim3 grid(NJT, N_ROWS / BM);                    // 192 x 16
    k_main<<<grid, 256, SMEM_BYTES>>>(targets, q_tgts);
    k_rows<<<RW_BLOCKS, 256>>>(targets, (float*)d_out);
}

// round 17
// speedup vs baseline: 1.4848x; 1.4848x over previous
#include <cuda_runtime.h>
#include <cuda_bf16.h>
#include <math.h>
#include <stdint.h>

// ---------------- problem shapes ----------------
#define N_ROWS   2048
#define DIM      512
#define NQ       3
#define KQ       8192
#define QK       (NQ * KQ)        // 24576
#define NCLS     16
#define NHB      32               // histogram partial blocks

// ---------------- GEMM tiling -------------------
#define BM   128                  // x rows per CTA
#define BN   128                  // q rows per CTA
#define BK   64                   // bf16 K per stage (128B rows = SW128 atom)
#define NJT  (QK / BN)            // 192 j-tiles
#define NT   (DIM / BK)           // 8 mainloop iters
#define NSTG 3

#define A_ST (BM * BK * 2)        // 16384 bytes/stage
#define B_ST (BN * BK * 2)        // 16384 bytes/stage
#define QTP_OFF  (NSTG * (A_ST + B_ST))         // 98304
#define RED_OFF  (QTP_OFF + 512)
#define RED_PITCH 5
#define SMEM_BYTES (RED_OFF + 2 * BM * RED_PITCH * 4)   // ~104KB

// k_rows config: one warp per row
#define RW_BLOCKS (N_ROWS / 8)    // 256 blocks x 8 warps

// ---------------- static device scratch ----------------
__device__ __align__(16) __nv_bfloat16 g_xb[N_ROWS * DIM];
__device__ __align__(16) __nv_bfloat16 g_qb[QK * DIM];
// TRANSPOSED partials: [row][jtile] so tail reduction is coalesced
__device__ float g_pt[N_ROWS * NJT];
__device__ float g_pm[N_ROWS * NJT];
__device__ float g_row[N_ROWS];
__device__ int   g_hpart[NHB * NCLS];
__device__ int   g_meta[4];   // [0]=targets is64, [1]=q_targets is64, [2]=order
__device__ int   g_tick;

__device__ __forceinline__ int load_tgt(const void* p, int i, int is64) {
    if (is64) return (int)((const long long*)p)[i];
    return ((const int*)p)[i];
}

// ---------------- helpers ----------------
__device__ __forceinline__ uint32_t smem_u32(const void* p) {
    uint32_t a;
    asm("{ .reg .u64 t; cvta.to.shared.u64 t, %1; cvt.u32.u64 %0, t; }" : "=r"(a) : "l"(p));
    return a;
}
__device__ __forceinline__ uint32_t swz(uint32_t o) { return o ^ ((o >> 3) & 0x70u); }

__device__ __forceinline__ void cpasync16(uint32_t s, const void* g) {
    asm volatile("cp.async.cg.shared.global [%0], [%1], 16;" :: "r"(s), "l"(g) : "memory");
}
__device__ __forceinline__ void cp_commit() {
    asm volatile("cp.async.commit_group;" ::: "memory");
}
__device__ __forceinline__ void cp_wait0() {
    asm volatile("cp.async.wait_group 0;" ::: "memory");
}
__device__ __forceinline__ void ldm4(uint32_t a, uint32_t& r0, uint32_t& r1,
                                     uint32_t& r2, uint32_t& r3) {
    asm volatile("ldmatrix.sync.aligned.m8n8.x4.shared.b16 {%0,%1,%2,%3}, [%4];"
                 : "=r"(r0), "=r"(r1), "=r"(r2), "=r"(r3) : "r"(a));
}
__device__ __forceinline__ void mma16816(float* c, const uint32_t* a, const uint32_t* b) {
    asm volatile(
        "mma.sync.aligned.m16n8k16.row.col.f32.bf16.bf16.f32 "
        "{%0,%1,%2,%3}, {%4,%5,%6,%7}, {%8,%9}, {%0,%1,%2,%3};"
        : "+f"(c[0]), "+f"(c[1]), "+f"(c[2]), "+f"(c[3])
        : "r"(a[0]), "r"(a[1]), "r"(a[2]), "r"(a[3]), "r"(b[0]), "r"(b[1]));
}

// ---------------- k_pre: meta detection + histogram partials ----------------
__global__ void k_pre(const void* targets, const void* q_targets, const void* order_p) {
    const int b = blockIdx.x, tid = threadIdx.x;
    if (b == NHB) {
        if (tid < 32) {
            unsigned v = ((const unsigned*)targets)[2 * tid + 1];
            unsigned any = __ballot_sync(0xffffffffu, v != 0u);
            if (tid == 0) g_meta[0] = (any == 0u) ? 1 : 0;
        }
        return;
    }
    __shared__ int hist_s[NCLS];
    unsigned w = ((const unsigned*)q_targets)[2 * (tid & 31) + 1];
    unsigned anyq = __ballot_sync(0xffffffffu, w != 0u);
    const int is64q = (anyq == 0u) ? 1 : 0;
    const int order = ((const int*)order_p)[0];   // low dword valid for i32/i64
    if (tid < NCLS) hist_s[tid] = 0;
    __syncthreads();
    const int i = b * 256 + tid;                  // 32*256 = 8192 = KQ
    int v = load_tgt(q_targets, order * KQ + i, is64q);
    atomicAdd(&hist_s[v], 1);
    __syncthreads();
    if (tid < NCLS) g_hpart[b * NCLS + tid] = hist_s[tid];
    if (b == 0 && tid == 0) { g_meta[1] = is64q; g_meta[2] = order; }
}

// ---------------- k_convert: L2-norm + bf16 cast (float4 loads) ----------------
__global__ void k_convert(const float* __restrict__ x, const float* __restrict__ q) {
    int warp = (blockIdx.x * blockDim.x + threadIdx.x) >> 5;
    int lane = threadIdx.x & 31;
    if (warp >= N_ROWS + QK) return;
    const float* src;
    __nv_bfloat16* dst;
    if (warp < N_ROWS) { src = x + (size_t)warp * DIM; dst = g_xb + (size_t)warp * DIM; }
    else { src = q + (size_t)(warp - N_ROWS) * DIM; dst = g_qb + (size_t)(warp - N_ROWS) * DIM; }
    const float4* s4 = (const float4*)src;
    float4 v[4];
    float s = 0.f;
    #pragma unroll
    for (int c = 0; c < 4; c++) {
        v[c] = s4[lane + c * 32];
        s += v[c].x * v[c].x + v[c].y * v[c].y + v[c].z * v[c].z + v[c].w * v[c].w;
    }
    #pragma unroll
    for (int o = 16; o > 0; o >>= 1) s += __shfl_xor_sync(0xffffffffu, s, o);
    float inv = 1.f / fmaxf(sqrtf(s), 1e-12f);
    uint2* d2 = (uint2*)dst;
    #pragma unroll
    for (int c = 0; c < 4; c++) {
        __nv_bfloat162 lo, hi;
        lo.x = __float2bfloat16_rn(v[c].x * inv);
        lo.y = __float2bfloat16_rn(v[c].y * inv);
        hi.x = __float2bfloat16_rn(v[c].z * inv);
        hi.y = __float2bfloat16_rn(v[c].w * inv);
        uint2 o2;
        o2.x = *(uint32_t*)&lo;
        o2.y = *(uint32_t*)&hi;
        d2[lane + c * 32] = o2;
    }
}

// ---------------- k_main: HMMA bf16 GEMM + fused exp epilogue ----------------
__global__ void __launch_bounds__(256, 2)
k_main(const void* __restrict__ targets, const void* __restrict__ q_targets) {
    extern __shared__ char smem_raw[];
    const uint32_t smem = smem_u32(smem_raw);
    const uint32_t aBase = smem;
    const uint32_t bBase = smem + NSTG * A_ST;
    int*   qtp  = (int*)(smem_raw + QTP_OFF);
    float* sm_s = (float*)(smem_raw + RED_OFF);
    float* sm_m = sm_s + BM * RED_PITCH;

    const int tid  = threadIdx.x;
    const int wid  = tid >> 5;
    const int lane = tid & 31;
    const int wm   = wid & 1;          // 2 warp-rows (64 M each)
    const int wn   = wid >> 1;         // 4 warp-cols (32 N each)
    const int i0   = blockIdx.y * BM;
    const int j0   = blockIdx.x * BN;

    const int is64t = g_meta[0];
    const int is64q = g_meta[1];
    const bool otile = (j0 / KQ) == g_meta[2];

    if (otile && tid < BN) qtp[tid] = load_tgt(q_targets, j0 + tid, is64q);

    // per-thread cp.async dest/src bases (immediate offsets per stage after unroll)
    uint32_t dstA[4];
    const char* srcA[4];
    const char* srcB[4];
    #pragma unroll
    for (int l = 0; l < 4; l++) {
        int idx = tid + l * 256, row = idx >> 3, c = idx & 7;
        dstA[l] = swz((uint32_t)(row * 128 + c * 16));
        srcA[l] = (const char*)(g_xb + ((size_t)(i0 + row) * DIM + c * 8));
        srcB[l] = (const char*)(g_qb + ((size_t)(j0 + row) * DIM + c * 8));
    }

    // ldmatrix per-lane byte offsets within a stage (ks -> XOR ks*32)
    uint32_t offA0[4], offB0[2];
    {
        int kc = lane >> 4;                 // 16B half
        #pragma unroll
        for (int m = 0; m < 4; m++) {
            int rowA = wm * 64 + m * 16 + (lane & 15);
            offA0[m] = swz((uint32_t)(rowA * 128 + kc * 16));
        }
        int kc2 = (lane >> 3) & 1;
        #pragma unroll
        for (int p = 0; p < 2; p++) {
            int rowB = wn * 32 + p * 16 + (lane & 7) + ((lane >> 4) & 1) * 8;
            offB0[p] = swz((uint32_t)(rowB * 128 + kc2 * 16));
        }
    }

    // hoisted epilogue row-target loads (hide latency behind the GEMM)
    const int l4  = lane >> 2;
    const int lm4 = lane & 3;
    int tgr[8];
    #pragma unroll
    for (int m = 0; m < 4; m++)
        #pragma unroll
        for (int half = 0; half < 2; half++)
            tgr[m * 2 + half] = load_tgt(targets, i0 + wm * 64 + m * 16 + half * 8 + l4, is64t);

    float c[4][4][4];
    #pragma unroll
    for (int m = 0; m < 4; m++)
        #pragma unroll
        for (int n = 0; n < 4; n++)
            #pragma unroll
            for (int e = 0; e < 4; e++) c[m][n][e] = 0.f;

    // register-double-buffered fragments
    uint32_t afr[2][4][4], bfr[2][4][2];

    // ---- prologue: stages 0,1; wait both, sync, preload ks0 of stage 0 ----
    #pragma unroll
    for (int s = 0; s < 2; s++) {
        #pragma unroll
        for (int l = 0; l < 4; l++) cpasync16(aBase + s * A_ST + dstA[l], srcA[l] + s * 128);
        #pragma unroll
        for (int l = 0; l < 4; l++) cpasync16(bBase + s * B_ST + dstA[l], srcB[l] + s * 128);
        cp_commit();
    }
    cp_wait0();
    __syncthreads();
    #pragma unroll
    for (int m = 0; m < 4; m++)
        ldm4(aBase + offA0[m], afr[0][m][0], afr[0][m][1], afr[0][m][2], afr[0][m][3]);
    #pragma unroll
    for (int p = 0; p < 2; p++)
        ldm4(bBase + offB0[p], bfr[0][2*p][0], bfr[0][2*p][1], bfr[0][2*p+1][0], bfr[0][2*p+1][1]);

    #pragma unroll
    for (int kt = 0; kt < NT; kt++) {
        const uint32_t aS = aBase + (kt % NSTG) * A_ST;
        const uint32_t bS = bBase + (kt % NSTG) * B_ST;
        const uint32_t aN = aBase + ((kt + 1) % NSTG) * A_ST;   // next stage (data already resident)
        const uint32_t bN = bBase + ((kt + 1) % NSTG) * B_ST;

        #pragma unroll
        for (int ks = 0; ks < 4; ks++) {
            const int cur = ks & 1;
            const int nxt = cur ^ 1;
            if (ks < 3) {
                const uint32_t kx = (ks + 1) * 32;
                #pragma unroll
                for (int m = 0; m < 4; m++)
                    ldm4(aS + (offA0[m] ^ kx), afr[nxt][m][0], afr[nxt][m][1],
                         afr[nxt][m][2], afr[nxt][m][3]);
                #pragma unroll
                for (int p = 0; p < 2; p++)
                    ldm4(bS + (offB0[p] ^ kx), bfr[nxt][2*p][0], bfr[nxt][2*p][1],
                         bfr[nxt][2*p+1][0], bfr[nxt][2*p+1][1]);
            } else if (kt + 1 < NT) {
                // cross-iteration prefetch: ks=0 fragments of stage kt+1 (published
                // by bottom-of-(kt-1) wait_group 0 + barrier)
                #pragma unroll
                for (int m = 0; m < 4; m++)
                    ldm4(aN + offA0[m], afr[nxt][m][0], afr[nxt][m][1],
                         afr[nxt][m][2], afr[nxt][m][3]);
                #pragma unroll
                for (int p = 0; p < 2; p++)
                    ldm4(bN + offB0[p], bfr[nxt][2*p][0], bfr[nxt][2*p][1],
                         bfr[nxt][2*p+1][0], bfr[nxt][2*p+1][1]);
            }
            #pragma unroll
            for (int m = 0; m < 4; m++)
                #pragma unroll
                for (int n = 0; n < 4; n++)
                    mma16816(c[m][n], afr[cur][m], bfr[cur][n]);

            // issue next-stage global prefetch after ks0's MMAs (LDSM-priority)
            if (ks == 0 && kt + 2 < NT) {
                const int s = (kt + 2) % NSTG;
                #pragma unroll
                for (int l = 0; l < 4; l++) cpasync16(aBase + s * A_ST + dstA[l], srcA[l] + (kt + 2) * 128);
                #pragma unroll
                for (int l = 0; l < 4; l++) cpasync16(bBase + s * B_ST + dstA[l], srcB[l] + (kt + 2) * 128);
                cp_commit();
            }
        }

        if (kt + 1 < NT) {
            cp_wait0();          // stage kt+2 resident (issued ~1 iter ago)
            __syncthreads();     // publish + protect stage reuse
        }
    }

    // ---- epilogue: exp + per-row (total, masked) partial sums ----
    int qtv[8];
    if (otile) {
        #pragma unroll
        for (int n = 0; n < 4; n++)
            #pragma unroll
            for (int e = 0; e < 2; e++)
                qtv[n * 2 + e] = qtp[wn * 32 + n * 8 + lm4 * 2 + e];
    }
    #pragma unroll
    for (int m = 0; m < 4; m++) {
        #pragma unroll
        for (int half = 0; half < 2; half++) {
            const int rl = wm * 64 + m * 16 + half * 8 + l4;   // local row
            const int tg = tgr[m * 2 + half];
            float s = 0.f, mk = 0.f;
            #pragma unroll
            for (int n = 0; n < 4; n++) {
                #pragma unroll
                for (int e = 0; e < 2; e++) {
                    float ex = __expf(fmaf(4.f, c[m][n][half * 2 + e], -4.f));
                    s += ex;
                    if (otile && qtv[n * 2 + e] == tg) mk += ex;
                }
            }
            s  += __shfl_xor_sync(0xffffffffu, s, 1);
            s  += __shfl_xor_sync(0xffffffffu, s, 2);
            mk += __shfl_xor_sync(0xffffffffu, mk, 1);
            mk += __shfl_xor_sync(0xffffffffu, mk, 2);
            if (lm4 == 0) {
                sm_s[rl * RED_PITCH + wn] = s;
                sm_m[rl * RED_PITCH + wn] = mk;
            }
        }
    }
    __syncthreads();
    if (tid < BM) {
        float tot = 0.f, msk = 0.f;
        #pragma unroll
        for (int w = 0; w < 4; w++) {
            tot += sm_s[tid * RED_PITCH + w];
            msk += sm_m[tid * RED_PITCH + w];
        }
        // transposed store: [row][jtile] -> coalesced tail reduction
        g_pt[(size_t)(i0 + tid) * NJT + blockIdx.x] = tot;
        g_pm[(size_t)(i0 + tid) * NJT + blockIdx.x] = msk;
    }
}

// ---------------- k_rows: warp-per-row (coalesced) + ticketed final sum ----
__global__ void __launch_bounds__(256)
k_rows(const void* __restrict__ targets, float* __restrict__ out) {
    const int tid  = threadIdx.x;
    const int wid  = tid >> 5;
    const int lane = tid & 31;
    __shared__ float cntS[NCLS];
    __shared__ int amLast;

    // per-class counts once per block (16 threads x 32 partials, L2-hot)
    if (tid < NCLS) {
        int c = QK;
        #pragma unroll
        for (int b = 0; b < NHB; b++) c -= g_hpart[b * NCLS + tid];
        cntS[tid] = (float)c;
    }
    __syncthreads();

    const int i = blockIdx.x * 8 + wid;    // one warp per row; 256 blocks x 8
    const float* pt = g_pt + (size_t)i * NJT;
    const float* pm = g_pm + (size_t)i * NJT;
    float t = 0.f, m = 0.f;
    #pragma unroll
    for (int u = 0; u < NJT / 32; u++) {   // 6 coalesced 128B loads per array
        t += pt[lane + u * 32];
        m += pm[lane + u * 32];
    }
    #pragma unroll
    for (int o = 16; o > 0; o >>= 1) {
        t += __shfl_xor_sync(0xffffffffu, t, o);
        m += __shfl_xor_sync(0xffffffffu, m, o);
    }
    if (lane == 0) {
        int tg = load_tgt(targets, i, g_meta[0]);
        g_row[i] = logf((t - m) / cntS[tg]);
    }

    // ticket: last block performs the deterministic final sum
    __threadfence();
    __syncthreads();
    if (tid == 0) amLast = (atomicAdd(&g_tick, 1) == RW_BLOCKS - 1);
    __syncthreads();
    if (amLast) {
        __shared__ float red[256];
        float s = 0.f;
        for (int k = tid; k < N_ROWS; k += 256) s += g_row[k];
        red[tid] = s;
        __syncthreads();
        for (int st = 128; st > 0; st >>= 1) {
            if (tid < st) red[tid] += red[tid + st];
            __syncthreads();
        }
        if (tid == 0) { out[0] = red[0] / (float)N_ROWS; g_tick = 0; }
    }
}

// ---------------- launch ----------------
extern "C" void kernel_launch(void* const* d_in, const int* in_sizes, int n_in,
                              void* d_out, int out_size) {
    const float* x       = (const float*)d_in[0];
    const float* q       = (const float*)d_in[1];
    const void*  targets = d_in[2];
    const void*  q_tgts  = d_in[3];
    const void*  order_p = d_in[4];

    cudaFuncSetAttribute(k_main, cudaFuncAttributeMaxDynamicSharedMemorySize, SMEM_BYTES);

    k_pre<<<NHB + 1, 256>>>(targets, q_tgts, order_p);
    {
        int total_warps = N_ROWS + QK;              // 26624
        int blocks = (total_warps + 7) / 8;
        k_convert<<<blocks, 256>>>(x, q);
    }
    dim3 grid(NJT, N_ROWS / BM);                    // 192 x 16
    k_main<<<grid, 256, SMEM_BYTES>>>(targets, q_tgts);
    k_rows<<<RW_BLOCKS, 256>>>(targets, (float*)d_out);
}